// round 12
// baseline (speedup 1.0000x reference)
#include <cuda_runtime.h>
#include <cuda_fp16.h>

#define N_USERS 100000
#define N_NODES 150000
#define E_MAX   4800000

// ---------------- static scratch (no allocation allowed) ----------------
__device__ int  d_counts[N_NODES];          // starts zeroed (.bss), self-zeroed in k_scan
__device__ int  d_rowptr[N_NODES + 1];
__device__ int  d_rank[E_MAX];              // intra-row rank of each edge
__device__ int4 d_perm4[E_MAX / 2 + 1];     // {col,val} pairs, 16B-aligned for LDG.128
#define d_perm ((int2*)d_perm4)
__device__ __half2 d_x16[2][N_NODES * 32];  // ping-pong fp16 copy of current x slice

// ------- fused: layer-0 embedding write + histogram (rank-recording) -------
#define GA 9375   // ceil(150000*16/256)

__global__ void k_init_hist(const float4* __restrict__ ue,
                            const float4* __restrict__ ie,
                            float4* __restrict__ out,
                            const int* __restrict__ rows, int e) {
    int b = blockIdx.x, t = threadIdx.x;
    if (b < GA) {
        int i = b * 256 + t;                 // over N_NODES*16
        if (i < N_NODES * 16) {
            int node = i >> 4, d4 = i & 15;
            float4 v = (node < N_USERS) ? ue[node * 16 + d4]
                                        : ie[(node - N_USERS) * 16 + d4];
            out[node * 64 + d4] = v;
            d_x16[0][node * 32 + 2 * d4]     = __floats2half2_rn(v.x, v.y);
            d_x16[0][node * 32 + 2 * d4 + 1] = __floats2half2_rn(v.z, v.w);
        }
    } else {
        int j = (b - GA) * 256 + t;
        if (j < e) {
            int r = __ldcs(&rows[j]);
            d_rank[j] = atomicAdd(&d_counts[r], 1);   // rank doubles as cursor
        }
    }
}

// ------- single-block exclusive scan of counts -> rowptr (int4, shfl-based) -------
__global__ __launch_bounds__(1024) void k_scan(int n) {
    __shared__ int wsum[32];
    __shared__ int carry_sh;
    int t = threadIdx.x, lane = t & 31, wid = t >> 5;
    if (t == 0) carry_sh = 0;
    __syncthreads();

    for (int base = 0; base < n; base += 4096) {
        int idx = base + t * 4;
        int4 c = make_int4(0, 0, 0, 0);
        if (idx + 3 < n) {
            c = *(int4*)&d_counts[idx];
            *(int4*)&d_counts[idx] = make_int4(0, 0, 0, 0);
        } else if (idx < n) {
            int* cp = &c.x;
            for (int j = 0; j < 4; ++j)
                if (idx + j < n) { cp[j] = d_counts[idx + j]; d_counts[idx + j] = 0; }
        }
        int tsum = c.x + c.y + c.z + c.w;

        int s = tsum;                                     // warp inclusive scan
        #pragma unroll
        for (int o = 1; o < 32; o <<= 1) {
            int x = __shfl_up_sync(0xffffffffu, s, o);
            if (lane >= o) s += x;
        }
        if (lane == 31) wsum[wid] = s;
        __syncthreads();
        if (wid == 0) {
            int ws = wsum[lane];
            #pragma unroll
            for (int o = 1; o < 32; o <<= 1) {
                int x = __shfl_up_sync(0xffffffffu, ws, o);
                if (lane >= o) ws += x;
            }
            wsum[lane] = ws;                              // inclusive warp sums
        }
        __syncthreads();
        int carry = carry_sh;
        int off = carry + (wid ? wsum[wid - 1] : 0) + (s - tsum);  // excl prefix
        int4 r;
        r.x = off; r.y = r.x + c.x; r.z = r.y + c.y; r.w = r.z + c.z;
        if (idx + 3 < n) {
            *(int4*)&d_rowptr[idx] = r;
        } else if (idx < n) {
            int* rp = &r.x;
            for (int j = 0; j < 4; ++j)
                if (idx + j < n) d_rowptr[idx + j] = rp[j];
        }
        __syncthreads();
        if (t == 1023) carry_sh = carry + wsum[31];       // add tile total
        __syncthreads();
    }
    if (t == 0) d_rowptr[n] = carry_sh;
}

// ---------------- scatter: atomic-free (rank precomputed) ----------------
__global__ void k_scatter(const int* __restrict__ rows,
                          const int* __restrict__ cols,
                          const float* __restrict__ vals, int e) {
    int i = blockIdx.x * blockDim.x + threadIdx.x;
    if (i < e) {
        int r = __ldcs(&rows[i]);
        int p = __ldg(&d_rowptr[r]) + __ldcs(&d_rank[i]);
        d_perm[p] = make_int2(__ldcs(&cols[i]), __float_as_int(__ldcs(&vals[i])));
    }
}

// ---------------- packed fp32x2 helpers (Blackwell) ----------------
__device__ __forceinline__ unsigned long long pack2(float a, float b) {
    unsigned long long r;
    asm("mov.b64 %0,{%1,%2};" : "=l"(r) : "f"(a), "f"(b));
    return r;
}
__device__ __forceinline__ void unpack2(unsigned long long v, float& a, float& b) {
    asm("mov.b64 {%0,%1},%2;" : "=f"(a), "=f"(b) : "l"(v));
}
__device__ __forceinline__ void ffma2(unsigned long long& acc, float s, float2 w) {
    asm("{\n\t"
        ".reg .b64 sa, wb;\n\t"
        "mov.b64 sa,{%1,%1};\n\t"
        "mov.b64 wb,{%2,%3};\n\t"
        "fma.rn.f32x2 %0, sa, wb, %0;\n\t"
        "}"
        : "+l"(acc) : "f"(s), "f"(w.x), "f"(w.y));
}

// ------- fused layer: gather(4 rows/warp) + shared fp16-W dense + leaky + L2-norm -------
// L1-wavefront reduction vs R11: perm via LDG.128 (2 edges/load, 32->16 wf/row)
// and fp16 W (LDS.32, 64->32 wf/row). Dense still batches 4 rows per W sweep.
__global__ __launch_bounds__(256, 4) void k_layer(
    const float* __restrict__ W1, const float* __restrict__ b1,
    const float* __restrict__ W2, const float* __restrict__ b2,
    float* out, int k, int rows_per_block, int write16)
{
    __shared__ __half2 Wsh[128 * 32];  // [i][l] = half2(Wt[i][2l], Wt[i][2l+1])
    __shared__ float bsh[64];
    __shared__ float ssh[8][4][128];   // per-warp, 4 rows of staged [msg | interact]

    int t = threadIdx.x, lane = t & 31, wid = t >> 5;
    int src = k & 1, dst = src ^ 1;
    const __half2* __restrict__ xs = d_x16[src];
    const int2* __restrict__ pm = d_perm;
    const int4* __restrict__ pm4 = d_perm4;

    const float* W1k = W1 + k * 4096;
    const float* W2k = W2 + k * 4096;
    // Wt[i][j] = (i<64) ? W1[k][j][i] : W2[k][j][i-64]
    for (int idx = t; idx < 128 * 32; idx += 256) {
        int i = idx >> 5, l = idx & 31;
        float w0, w1;
        if (i < 64) { w0 = W1k[(2 * l) * 64 + i];      w1 = W1k[(2 * l + 1) * 64 + i]; }
        else        { w0 = W2k[(2 * l) * 64 + i - 64]; w1 = W2k[(2 * l + 1) * 64 + i - 64]; }
        Wsh[idx] = __floats2half2_rn(w0, w1);
    }
    if (t < 64) bsh[t] = b1[k * 64 + t] + b2[k * 64 + t];
    __syncthreads();

    const int koff = k * 64;
    int r0 = blockIdx.x * rows_per_block;
    int r1 = min(r0 + rows_per_block, N_NODES);

    for (int gbase = r0 + wid * 4; gbase < r1; gbase += 32) {
        // ---- gather 4 rows (full warp per row; int4 perm, unroll-8 MLP) ----
        #pragma unroll 1
        for (int rr = 0; rr < 4; ++rr) {
            int r = gbase + rr;
            int start = 0, stop = 0;
            if (r < r1) {
                start = __ldg(&d_rowptr[r]);
                stop  = __ldg(&d_rowptr[r + 1]);
            }
            unsigned long long accA = 0ull, accB = 0ull;
            int e = start;
            if ((e & 1) && e < stop) {                 // align to int4 boundary
                int2 cv = __ldcs(&pm[e]);
                __half2 h = __ldcg(&xs[(size_t)cv.x * 32 + lane]);
                ffma2(accA, __int_as_float(cv.y), __half22float2(h));
                ++e;
            }
            #pragma unroll 1
            for (; e + 8 <= stop; e += 8) {
                int4 p01 = __ldcs(&pm4[(e >> 1) + 0]);
                int4 p23 = __ldcs(&pm4[(e >> 1) + 1]);
                int4 p45 = __ldcs(&pm4[(e >> 1) + 2]);
                int4 p67 = __ldcs(&pm4[(e >> 1) + 3]);
                __half2 h0 = __ldcg(&xs[(size_t)p01.x * 32 + lane]);
                __half2 h1 = __ldcg(&xs[(size_t)p01.z * 32 + lane]);
                __half2 h2 = __ldcg(&xs[(size_t)p23.x * 32 + lane]);
                __half2 h3 = __ldcg(&xs[(size_t)p23.z * 32 + lane]);
                __half2 h4 = __ldcg(&xs[(size_t)p45.x * 32 + lane]);
                __half2 h5 = __ldcg(&xs[(size_t)p45.z * 32 + lane]);
                __half2 h6 = __ldcg(&xs[(size_t)p67.x * 32 + lane]);
                __half2 h7 = __ldcg(&xs[(size_t)p67.z * 32 + lane]);
                ffma2(accA, __int_as_float(p01.y), __half22float2(h0));
                ffma2(accB, __int_as_float(p01.w), __half22float2(h1));
                ffma2(accA, __int_as_float(p23.y), __half22float2(h2));
                ffma2(accB, __int_as_float(p23.w), __half22float2(h3));
                ffma2(accA, __int_as_float(p45.y), __half22float2(h4));
                ffma2(accB, __int_as_float(p45.w), __half22float2(h5));
                ffma2(accA, __int_as_float(p67.y), __half22float2(h6));
                ffma2(accB, __int_as_float(p67.w), __half22float2(h7));
            }
            #pragma unroll 1
            for (; e < stop; ++e) {
                int2 cv = __ldcs(&pm[e]);
                __half2 h = __ldcg(&xs[(size_t)cv.x * 32 + lane]);
                ffma2(accA, __int_as_float(cv.y), __half22float2(h));
            }
            float a0, a1, b0v, b1v;
            unpack2(accA, a0, a1);
            unpack2(accB, b0v, b1v);
            a0 += b0v;
            a1 += b1v;
            float2 xr = make_float2(0.f, 0.f);
            if (r < r1)
                xr = *(const float2*)(out + (size_t)r * 256 + koff + 2 * lane);
            float* s = ssh[wid][rr];
            *(float2*)&s[2 * lane]      = make_float2(a0, a1);
            *(float2*)&s[64 + 2 * lane] = make_float2(a0 * xr.x, a1 * xr.y);
        }
        __syncwarp();

        // ---- dense: 4 rows share each W read; lane owns outputs 2l, 2l+1 ----
        unsigned long long binit = pack2(bsh[2 * lane], bsh[2 * lane + 1]);
        unsigned long long acc0 = binit, acc1 = binit, acc2 = binit, acc3 = binit;
        const __half2* Wp = Wsh + lane;                 // row i at Wp[i*32]
        const float (*sb)[128] = ssh[wid];
        #pragma unroll
        for (int i = 0; i < 128; i += 4) {
            float2 w0 = __half22float2(Wp[(i + 0) * 32]);
            float2 w1 = __half22float2(Wp[(i + 1) * 32]);
            float2 w2 = __half22float2(Wp[(i + 2) * 32]);
            float2 w3 = __half22float2(Wp[(i + 3) * 32]);
            float4 sA = *(const float4*)&sb[0][i];
            float4 sB = *(const float4*)&sb[1][i];
            float4 sC = *(const float4*)&sb[2][i];
            float4 sD = *(const float4*)&sb[3][i];
            ffma2(acc0, sA.x, w0); ffma2(acc0, sA.y, w1);
            ffma2(acc0, sA.z, w2); ffma2(acc0, sA.w, w3);
            ffma2(acc1, sB.x, w0); ffma2(acc1, sB.y, w1);
            ffma2(acc1, sB.z, w2); ffma2(acc1, sB.w, w3);
            ffma2(acc2, sC.x, w0); ffma2(acc2, sC.y, w1);
            ffma2(acc2, sC.z, w2); ffma2(acc2, sC.w, w3);
            ffma2(acc3, sD.x, w0); ffma2(acc3, sD.y, w1);
            ffma2(acc3, sD.z, w2); ffma2(acc3, sD.w, w3);
        }

        // ---- epilogue per row: leaky + warp L2-norm + writes ----
        unsigned long long accs[4] = {acc0, acc1, acc2, acc3};
        #pragma unroll
        for (int rr = 0; rr < 4; ++rr) {
            int r = gbase + rr;
            float h0, h1;
            unpack2(accs[rr], h0, h1);
            h0 = h0 > 0.f ? h0 : 0.2f * h0;             // leaky_relu(0.2)
            h1 = h1 > 0.f ? h1 : 0.2f * h1;
            float sq = h0 * h0 + h1 * h1;
            #pragma unroll
            for (int mm = 16; mm; mm >>= 1)
                sq += __shfl_xor_sync(0xffffffffu, sq, mm);
            float inv = 1.0f / fmaxf(sqrtf(sq), 1e-12f);
            float o0 = h0 * inv, o1 = h1 * inv;
            if (r < r1) {
                *(float2*)(out + (size_t)r * 256 + koff + 64 + 2 * lane) =
                    make_float2(o0, o1);
                if (write16)
                    d_x16[dst][(size_t)r * 32 + lane] = __floats2half2_rn(o0, o1);
            }
        }
        __syncwarp();
    }
}

// ---------------- launch ----------------
extern "C" void kernel_launch(void* const* d_in, const int* in_sizes, int n_in,
                              void* d_out, int out_size) {
    const float* ue   = (const float*)d_in[0];
    const float* ie   = (const float*)d_in[1];
    const float* W1   = (const float*)d_in[2];
    const float* b1   = (const float*)d_in[3];
    const float* W2   = (const float*)d_in[4];
    const float* b2   = (const float*)d_in[5];
    const float* vals = (const float*)d_in[6];
    const int*   rows = (const int*)d_in[7];
    const int*   cols = (const int*)d_in[8];
    float* out = (float*)d_out;
    int e = in_sizes[6];
    int L = in_sizes[2] / (64 * 64);

    // 0) layer-0 embeddings + histogram w/ rank recording
    int GB = (e + 255) / 256;
    k_init_hist<<<GA + GB, 256>>>((const float4*)ue, (const float4*)ie,
                                  (float4*)out, rows, e);
    // 1) rowptr scan (counts self-zeroed)
    k_scan<<<1, 1024>>>(N_NODES);
    // 2) atomic-free scatter
    k_scatter<<<(e + 255) / 256, 256>>>(rows, cols, vals, e);

    // 3-5) fused layers — 592 blocks = 4/SM on 148 SMs = one wave
    const int DG = 592;
    const int rpb = (N_NODES + DG - 1) / DG;             // 254
    for (int k = 0; k < L; ++k)
        k_layer<<<DG, 256>>>(W1, b1, W2, b2, out, k, rpb, (k + 1 < L) ? 1 : 0);
}

// round 13
// speedup vs baseline: 1.0646x; 1.0646x over previous
#include <cuda_runtime.h>
#include <cuda_fp16.h>

#define N_USERS 100000
#define N_NODES 150000
#define E_MAX   4800000

// ---------------- static scratch (no allocation allowed) ----------------
__device__ int  d_counts[N_NODES];          // starts zeroed (.bss), self-zeroed in k_scan
__device__ int  d_rowptr[N_NODES + 1];
__device__ int  d_rank[E_MAX];              // intra-row rank of each edge
__device__ int2 d_perm[E_MAX];              // {col, val_bits} interleaved
__device__ __half2 d_x16[2][N_NODES * 32];  // ping-pong fp16 copy of current x slice

// ------- fused: layer-0 embedding write + histogram (rank-recording) -------
#define GA 9375   // ceil(150000*16/256)

__global__ void k_init_hist(const float4* __restrict__ ue,
                            const float4* __restrict__ ie,
                            float4* __restrict__ out,
                            const int* __restrict__ rows, int e) {
    int b = blockIdx.x, t = threadIdx.x;
    if (b < GA) {
        int i = b * 256 + t;                 // over N_NODES*16
        if (i < N_NODES * 16) {
            int node = i >> 4, d4 = i & 15;
            float4 v = (node < N_USERS) ? ue[node * 16 + d4]
                                        : ie[(node - N_USERS) * 16 + d4];
            out[node * 64 + d4] = v;
            d_x16[0][node * 32 + 2 * d4]     = __floats2half2_rn(v.x, v.y);
            d_x16[0][node * 32 + 2 * d4 + 1] = __floats2half2_rn(v.z, v.w);
        }
    } else {
        int j = (b - GA) * 256 + t;
        if (j < e) {
            int r = __ldcs(&rows[j]);
            d_rank[j] = atomicAdd(&d_counts[r], 1);   // rank doubles as cursor
        }
    }
}

// ------- single-block exclusive scan of counts -> rowptr (int4, shfl-based) -------
__global__ __launch_bounds__(1024) void k_scan(int n) {
    __shared__ int wsum[32];
    __shared__ int carry_sh;
    int t = threadIdx.x, lane = t & 31, wid = t >> 5;
    if (t == 0) carry_sh = 0;
    __syncthreads();

    for (int base = 0; base < n; base += 4096) {
        int idx = base + t * 4;
        int4 c = make_int4(0, 0, 0, 0);
        if (idx + 3 < n) {
            c = *(int4*)&d_counts[idx];
            *(int4*)&d_counts[idx] = make_int4(0, 0, 0, 0);
        } else if (idx < n) {
            int* cp = &c.x;
            for (int j = 0; j < 4; ++j)
                if (idx + j < n) { cp[j] = d_counts[idx + j]; d_counts[idx + j] = 0; }
        }
        int tsum = c.x + c.y + c.z + c.w;

        int s = tsum;                                     // warp inclusive scan
        #pragma unroll
        for (int o = 1; o < 32; o <<= 1) {
            int x = __shfl_up_sync(0xffffffffu, s, o);
            if (lane >= o) s += x;
        }
        if (lane == 31) wsum[wid] = s;
        __syncthreads();
        if (wid == 0) {
            int ws = wsum[lane];
            #pragma unroll
            for (int o = 1; o < 32; o <<= 1) {
                int x = __shfl_up_sync(0xffffffffu, ws, o);
                if (lane >= o) ws += x;
            }
            wsum[lane] = ws;                              // inclusive warp sums
        }
        __syncthreads();
        int carry = carry_sh;
        int off = carry + (wid ? wsum[wid - 1] : 0) + (s - tsum);  // excl prefix
        int4 r;
        r.x = off; r.y = r.x + c.x; r.z = r.y + c.y; r.w = r.z + c.z;
        if (idx + 3 < n) {
            *(int4*)&d_rowptr[idx] = r;
        } else if (idx < n) {
            int* rp = &r.x;
            for (int j = 0; j < 4; ++j)
                if (idx + j < n) d_rowptr[idx + j] = rp[j];
        }
        __syncthreads();
        if (t == 1023) carry_sh = carry + wsum[31];       // add tile total
        __syncthreads();
    }
    if (t == 0) d_rowptr[n] = carry_sh;
}

// ---------------- scatter: atomic-free (rank precomputed) ----------------
__global__ void k_scatter(const int* __restrict__ rows,
                          const int* __restrict__ cols,
                          const float* __restrict__ vals, int e) {
    int i = blockIdx.x * blockDim.x + threadIdx.x;
    if (i < e) {
        int r = __ldcs(&rows[i]);
        int p = __ldg(&d_rowptr[r]) + __ldcs(&d_rank[i]);
        d_perm[p] = make_int2(__ldcs(&cols[i]), __float_as_int(__ldcs(&vals[i])));
    }
}

// ---------------- packed fp32x2 helpers (Blackwell) ----------------
__device__ __forceinline__ unsigned long long pack2(float a, float b) {
    unsigned long long r;
    asm("mov.b64 %0,{%1,%2};" : "=l"(r) : "f"(a), "f"(b));
    return r;
}
__device__ __forceinline__ void unpack2(unsigned long long v, float& a, float& b) {
    asm("mov.b64 {%0,%1},%2;" : "=f"(a), "=f"(b) : "l"(v));
}
__device__ __forceinline__ void ffma2(unsigned long long& acc, float s, float2 w) {
    asm("{\n\t"
        ".reg .b64 sa, wb;\n\t"
        "mov.b64 sa,{%1,%1};\n\t"
        "mov.b64 wb,{%2,%3};\n\t"
        "fma.rn.f32x2 %0, sa, wb, %0;\n\t"
        "}"
        : "+l"(acc) : "f"(s), "f"(w.x), "f"(w.y));
}

// ------- fused layer: shfl-perm pipelined gather + shared-W dense + leaky + L2-norm ----
// Gather chain was serial perm-load(250cyc) -> x-gather(250cyc) per batch.
// Now: ONE distributed perm load per 32 edges (lane l holds edge start+l; shfl
// broadcasts), and gather batches are double-buffered so batch b+1's loads
// issue before batch b's FFMAs consume. Dense: 4 rows share fp32 W (R11-best).
__global__ __launch_bounds__(256, 4) void k_layer(
    const float* __restrict__ W1, const float* __restrict__ b1,
    const float* __restrict__ W2, const float* __restrict__ b2,
    float* out, int k, int rows_per_block, int write16)
{
    __shared__ float2 Wsh[128 * 32];   // [i][l] = float2(Wt[i][2l], Wt[i][2l+1])
    __shared__ float bsh[64];
    __shared__ float ssh[8][4][128];   // per-warp, 4 rows of staged [msg | interact]

    int t = threadIdx.x, lane = t & 31, wid = t >> 5;
    int src = k & 1, dst = src ^ 1;
    const __half2* __restrict__ xs = d_x16[src];
    const int2* __restrict__ pm = d_perm;

    const float* W1k = W1 + k * 4096;
    const float* W2k = W2 + k * 4096;
    // Wt[i][j] = (i<64) ? W1[k][j][i] : W2[k][j][i-64]
    for (int idx = t; idx < 128 * 32; idx += 256) {
        int i = idx >> 5, l = idx & 31;
        float w0, w1;
        if (i < 64) { w0 = W1k[(2 * l) * 64 + i];      w1 = W1k[(2 * l + 1) * 64 + i]; }
        else        { w0 = W2k[(2 * l) * 64 + i - 64]; w1 = W2k[(2 * l + 1) * 64 + i - 64]; }
        Wsh[idx] = make_float2(w0, w1);
    }
    if (t < 64) bsh[t] = b1[k * 64 + t] + b2[k * 64 + t];
    __syncthreads();

    const int koff = k * 64;
    int r0 = blockIdx.x * rows_per_block;
    int r1 = min(r0 + rows_per_block, N_NODES);

    for (int gbase = r0 + wid * 4; gbase < r1; gbase += 32) {
        // ---- gather 4 rows ----
        #pragma unroll 1
        for (int rr = 0; rr < 4; ++rr) {
            int r = gbase + rr;
            int start = 0, stop = 0;
            if (r < r1) {
                start = __ldg(&d_rowptr[r]);
                stop  = __ldg(&d_rowptr[r + 1]);
            }
            unsigned long long accA = 0ull, accB = 0ull;

            int eb = start;
            #pragma unroll 1
            while (eb < stop) {
                // one distributed load covers the next 32 edges
                int2 myp = (eb + lane < stop) ? __ldcs(&pm[eb + lane])
                                              : make_int2(0, 0);
                int cnt = min(32, stop - eb);
                int nb = (cnt + 7) >> 3;            // zero-padded batches of 8

                float vA[8]; __half2 hA[8];
                #pragma unroll
                for (int q = 0; q < 8; ++q) {       // load batch 0
                    int col = __shfl_sync(0xffffffffu, myp.x, q);
                    vA[q] = __uint_as_float(
                        (unsigned)__shfl_sync(0xffffffffu, myp.y, q));
                    hA[q] = __ldcg(&xs[(size_t)col * 32 + lane]);
                }
                #pragma unroll 1
                for (int b = 1; b < nb; ++b) {
                    float vB[8]; __half2 hB[8];
                    int b8 = b * 8;
                    #pragma unroll
                    for (int q = 0; q < 8; ++q) {   // load batch b
                        int col = __shfl_sync(0xffffffffu, myp.x, b8 + q);
                        vB[q] = __uint_as_float(
                            (unsigned)__shfl_sync(0xffffffffu, myp.y, b8 + q));
                        hB[q] = __ldcg(&xs[(size_t)col * 32 + lane]);
                    }
                    #pragma unroll
                    for (int q = 0; q < 8; q += 2) { // consume batch b-1
                        ffma2(accA, vA[q],     __half22float2(hA[q]));
                        ffma2(accB, vA[q + 1], __half22float2(hA[q + 1]));
                    }
                    #pragma unroll
                    for (int q = 0; q < 8; ++q) { vA[q] = vB[q]; hA[q] = hB[q]; }
                }
                #pragma unroll
                for (int q = 0; q < 8; q += 2) {     // consume last batch
                    ffma2(accA, vA[q],     __half22float2(hA[q]));
                    ffma2(accB, vA[q + 1], __half22float2(hA[q + 1]));
                }
                eb += 32;
            }

            float a0, a1, b0v, b1v;
            unpack2(accA, a0, a1);
            unpack2(accB, b0v, b1v);
            a0 += b0v;
            a1 += b1v;
            float2 xr = make_float2(0.f, 0.f);
            if (r < r1)
                xr = *(const float2*)(out + (size_t)r * 256 + koff + 2 * lane);
            float* s = ssh[wid][rr];
            *(float2*)&s[2 * lane]      = make_float2(a0, a1);
            *(float2*)&s[64 + 2 * lane] = make_float2(a0 * xr.x, a1 * xr.y);
        }
        __syncwarp();

        // ---- dense: 4 rows share each W read; lane owns outputs 2l, 2l+1 ----
        unsigned long long binit = pack2(bsh[2 * lane], bsh[2 * lane + 1]);
        unsigned long long acc0 = binit, acc1 = binit, acc2 = binit, acc3 = binit;
        const float2* Wp = Wsh + lane;                  // row i at Wp[i*32]
        const float (*sb)[128] = ssh[wid];
        #pragma unroll
        for (int i = 0; i < 128; i += 4) {
            float2 w0 = Wp[(i + 0) * 32];
            float2 w1 = Wp[(i + 1) * 32];
            float2 w2 = Wp[(i + 2) * 32];
            float2 w3 = Wp[(i + 3) * 32];
            float4 sA = *(const float4*)&sb[0][i];
            float4 sB = *(const float4*)&sb[1][i];
            float4 sC = *(const float4*)&sb[2][i];
            float4 sD = *(const float4*)&sb[3][i];
            ffma2(acc0, sA.x, w0); ffma2(acc0, sA.y, w1);
            ffma2(acc0, sA.z, w2); ffma2(acc0, sA.w, w3);
            ffma2(acc1, sB.x, w0); ffma2(acc1, sB.y, w1);
            ffma2(acc1, sB.z, w2); ffma2(acc1, sB.w, w3);
            ffma2(acc2, sC.x, w0); ffma2(acc2, sC.y, w1);
            ffma2(acc2, sC.z, w2); ffma2(acc2, sC.w, w3);
            ffma2(acc3, sD.x, w0); ffma2(acc3, sD.y, w1);
            ffma2(acc3, sD.z, w2); ffma2(acc3, sD.w, w3);
        }

        // ---- epilogue per row: leaky + warp L2-norm + writes ----
        unsigned long long accs[4] = {acc0, acc1, acc2, acc3};
        #pragma unroll
        for (int rr = 0; rr < 4; ++rr) {
            int r = gbase + rr;
            float h0, h1;
            unpack2(accs[rr], h0, h1);
            h0 = h0 > 0.f ? h0 : 0.2f * h0;             // leaky_relu(0.2)
            h1 = h1 > 0.f ? h1 : 0.2f * h1;
            float sq = h0 * h0 + h1 * h1;
            #pragma unroll
            for (int mm = 16; mm; mm >>= 1)
                sq += __shfl_xor_sync(0xffffffffu, sq, mm);
            float inv = 1.0f / fmaxf(sqrtf(sq), 1e-12f);
            float o0 = h0 * inv, o1 = h1 * inv;
            if (r < r1) {
                *(float2*)(out + (size_t)r * 256 + koff + 64 + 2 * lane) =
                    make_float2(o0, o1);
                if (write16)
                    d_x16[dst][(size_t)r * 32 + lane] = __floats2half2_rn(o0, o1);
            }
        }
        __syncwarp();
    }
}

// ---------------- launch ----------------
extern "C" void kernel_launch(void* const* d_in, const int* in_sizes, int n_in,
                              void* d_out, int out_size) {
    const float* ue   = (const float*)d_in[0];
    const float* ie   = (const float*)d_in[1];
    const float* W1   = (const float*)d_in[2];
    const float* b1   = (const float*)d_in[3];
    const float* W2   = (const float*)d_in[4];
    const float* b2   = (const float*)d_in[5];
    const float* vals = (const float*)d_in[6];
    const int*   rows = (const int*)d_in[7];
    const int*   cols = (const int*)d_in[8];
    float* out = (float*)d_out;
    int e = in_sizes[6];
    int L = in_sizes[2] / (64 * 64);

    // 0) layer-0 embeddings + histogram w/ rank recording
    int GB = (e + 255) / 256;
    k_init_hist<<<GA + GB, 256>>>((const float4*)ue, (const float4*)ie,
                                  (float4*)out, rows, e);
    // 1) rowptr scan (counts self-zeroed)
    k_scan<<<1, 1024>>>(N_NODES);
    // 2) atomic-free scatter
    k_scatter<<<(e + 255) / 256, 256>>>(rows, cols, vals, e);

    // 3-5) fused layers — 592 blocks = 4/SM on 148 SMs = one wave
    const int DG = 592;
    const int rpb = (N_NODES + DG - 1) / DG;             // 254
    for (int k = 0; k < L; ++k)
        k_layer<<<DG, 256>>>(W1, b1, W2, b2, out, k, rpb, (k + 1 < L) ? 1 : 0);
}

// round 14
// speedup vs baseline: 1.0929x; 1.0266x over previous
#include <cuda_runtime.h>
#include <cuda_fp16.h>

#define N_USERS 100000
#define N_NODES 150000
#define E_MAX   4800000

// ---------------- static scratch (no allocation allowed) ----------------
__device__ int  d_counts[N_NODES];          // starts zeroed (.bss), self-zeroed in k_scan
__device__ int  d_rowptr[N_NODES + 1];
__device__ int  d_rank[E_MAX];              // intra-row rank of each edge
__device__ int2 d_perm[E_MAX];              // {col, val_bits} interleaved
__device__ __half2 d_x16[2][N_NODES * 32];  // ping-pong fp16 copy of current x slice
__device__ __half2 d_msg16[N_NODES * 32];   // fp16 msg scratch between spmm and dense

// ------- fused: layer-0 embedding write + histogram (rank-recording) -------
#define GA 9375   // ceil(150000*16/256)

__global__ void k_init_hist(const float4* __restrict__ ue,
                            const float4* __restrict__ ie,
                            float4* __restrict__ out,
                            const int* __restrict__ rows, int e) {
    int b = blockIdx.x, t = threadIdx.x;
    if (b < GA) {
        int i = b * 256 + t;                 // over N_NODES*16
        if (i < N_NODES * 16) {
            int node = i >> 4, d4 = i & 15;
            float4 v = (node < N_USERS) ? ue[node * 16 + d4]
                                        : ie[(node - N_USERS) * 16 + d4];
            out[node * 64 + d4] = v;
            d_x16[0][node * 32 + 2 * d4]     = __floats2half2_rn(v.x, v.y);
            d_x16[0][node * 32 + 2 * d4 + 1] = __floats2half2_rn(v.z, v.w);
        }
    } else {
        int j = (b - GA) * 256 + t;
        if (j < e) {
            int r = __ldcs(&rows[j]);
            d_rank[j] = atomicAdd(&d_counts[r], 1);   // rank doubles as cursor
        }
    }
}

// ------- single-block exclusive scan of counts -> rowptr (int4, shfl-based) -------
__global__ __launch_bounds__(1024) void k_scan(int n) {
    __shared__ int wsum[32];
    __shared__ int carry_sh;
    int t = threadIdx.x, lane = t & 31, wid = t >> 5;
    if (t == 0) carry_sh = 0;
    __syncthreads();

    for (int base = 0; base < n; base += 4096) {
        int idx = base + t * 4;
        int4 c = make_int4(0, 0, 0, 0);
        if (idx + 3 < n) {
            c = *(int4*)&d_counts[idx];
            *(int4*)&d_counts[idx] = make_int4(0, 0, 0, 0);
        } else if (idx < n) {
            int* cp = &c.x;
            for (int j = 0; j < 4; ++j)
                if (idx + j < n) { cp[j] = d_counts[idx + j]; d_counts[idx + j] = 0; }
        }
        int tsum = c.x + c.y + c.z + c.w;

        int s = tsum;                                     // warp inclusive scan
        #pragma unroll
        for (int o = 1; o < 32; o <<= 1) {
            int x = __shfl_up_sync(0xffffffffu, s, o);
            if (lane >= o) s += x;
        }
        if (lane == 31) wsum[wid] = s;
        __syncthreads();
        if (wid == 0) {
            int ws = wsum[lane];
            #pragma unroll
            for (int o = 1; o < 32; o <<= 1) {
                int x = __shfl_up_sync(0xffffffffu, ws, o);
                if (lane >= o) ws += x;
            }
            wsum[lane] = ws;                              // inclusive warp sums
        }
        __syncthreads();
        int carry = carry_sh;
        int off = carry + (wid ? wsum[wid - 1] : 0) + (s - tsum);  // excl prefix
        int4 r;
        r.x = off; r.y = r.x + c.x; r.z = r.y + c.y; r.w = r.z + c.z;
        if (idx + 3 < n) {
            *(int4*)&d_rowptr[idx] = r;
        } else if (idx < n) {
            int* rp = &r.x;
            for (int j = 0; j < 4; ++j)
                if (idx + j < n) d_rowptr[idx + j] = rp[j];
        }
        __syncthreads();
        if (t == 1023) carry_sh = carry + wsum[31];       // add tile total
        __syncthreads();
    }
    if (t == 0) d_rowptr[n] = carry_sh;
}

// ---------------- scatter: atomic-free (rank precomputed) ----------------
__global__ void k_scatter(const int* __restrict__ rows,
                          const int* __restrict__ cols,
                          const float* __restrict__ vals, int e) {
    int i = blockIdx.x * blockDim.x + threadIdx.x;
    if (i < e) {
        int r = __ldcs(&rows[i]);
        int p = __ldg(&d_rowptr[r]) + __ldcs(&d_rank[i]);
        d_perm[p] = make_int2(__ldcs(&cols[i]), __float_as_int(__ldcs(&vals[i])));
    }
}

// ---------------- packed fp32x2 helpers (Blackwell) ----------------
__device__ __forceinline__ unsigned long long pack2(float a, float b) {
    unsigned long long r;
    asm("mov.b64 %0,{%1,%2};" : "=l"(r) : "f"(a), "f"(b));
    return r;
}
__device__ __forceinline__ void unpack2(unsigned long long v, float& a, float& b) {
    asm("mov.b64 {%0,%1},%2;" : "=f"(a), "=f"(b) : "l"(v));
}
__device__ __forceinline__ void ffma2(unsigned long long& acc, float s, float2 w) {
    asm("{\n\t"
        ".reg .b64 sa, wb;\n\t"
        "mov.b64 sa,{%1,%1};\n\t"
        "mov.b64 wb,{%2,%3};\n\t"
        "fma.rn.f32x2 %0, sa, wb, %0;\n\t"
        "}"
        : "+l"(acc) : "f"(s), "f"(w.x), "f"(w.y));
}

// ---------------- SpMM-only kernel: max residency, no smem ----------------
// warp per row; lane owns dims 2l,2l+1; unroll-8 for MLP; writes msg fp16.
__global__ __launch_bounds__(256, 5) void k_spmm(int srck, int rows_per_block) {
    int t = threadIdx.x, lane = t & 31, wid = t >> 5;
    const __half2* __restrict__ xs = d_x16[srck];
    const int2* __restrict__ pm = d_perm;

    int r0 = blockIdx.x * rows_per_block;
    int r1 = min(r0 + rows_per_block, N_NODES);

    for (int r = r0 + wid; r < r1; r += 8) {
        int start = __ldg(&d_rowptr[r]);
        int stop  = __ldg(&d_rowptr[r + 1]);
        unsigned long long accA = 0ull, accB = 0ull;
        int e = start;
        #pragma unroll 1
        for (; e + 8 <= stop; e += 8) {
            int2 cv0 = __ldcs(&pm[e + 0]);
            int2 cv1 = __ldcs(&pm[e + 1]);
            int2 cv2 = __ldcs(&pm[e + 2]);
            int2 cv3 = __ldcs(&pm[e + 3]);
            int2 cv4 = __ldcs(&pm[e + 4]);
            int2 cv5 = __ldcs(&pm[e + 5]);
            int2 cv6 = __ldcs(&pm[e + 6]);
            int2 cv7 = __ldcs(&pm[e + 7]);
            __half2 h0 = __ldcg(&xs[(size_t)cv0.x * 32 + lane]);
            __half2 h1 = __ldcg(&xs[(size_t)cv1.x * 32 + lane]);
            __half2 h2 = __ldcg(&xs[(size_t)cv2.x * 32 + lane]);
            __half2 h3 = __ldcg(&xs[(size_t)cv3.x * 32 + lane]);
            __half2 h4 = __ldcg(&xs[(size_t)cv4.x * 32 + lane]);
            __half2 h5 = __ldcg(&xs[(size_t)cv5.x * 32 + lane]);
            __half2 h6 = __ldcg(&xs[(size_t)cv6.x * 32 + lane]);
            __half2 h7 = __ldcg(&xs[(size_t)cv7.x * 32 + lane]);
            ffma2(accA, __int_as_float(cv0.y), __half22float2(h0));
            ffma2(accB, __int_as_float(cv1.y), __half22float2(h1));
            ffma2(accA, __int_as_float(cv2.y), __half22float2(h2));
            ffma2(accB, __int_as_float(cv3.y), __half22float2(h3));
            ffma2(accA, __int_as_float(cv4.y), __half22float2(h4));
            ffma2(accB, __int_as_float(cv5.y), __half22float2(h5));
            ffma2(accA, __int_as_float(cv6.y), __half22float2(h6));
            ffma2(accB, __int_as_float(cv7.y), __half22float2(h7));
        }
        #pragma unroll 1
        for (; e < stop; ++e) {
            int2 cv = __ldcs(&pm[e]);
            __half2 h = __ldcg(&xs[(size_t)cv.x * 32 + lane]);
            ffma2(accA, __int_as_float(cv.y), __half22float2(h));
        }
        float a0, a1, b0v, b1v;
        unpack2(accA, a0, a1);
        unpack2(accB, b0v, b1v);
        d_msg16[(size_t)r * 32 + lane] = __floats2half2_rn(a0 + b0v, a1 + b1v);
    }
}

// ------- dense-only kernel: 4 rows share each W read + leaky + L2-norm -------
__global__ __launch_bounds__(256, 4) void k_dense(
    const float* __restrict__ W1, const float* __restrict__ b1,
    const float* __restrict__ W2, const float* __restrict__ b2,
    float* out, int k, int rows_per_block, int write16)
{
    __shared__ float2 Wsh[128 * 32];   // [i][l] = float2(Wt[i][2l], Wt[i][2l+1])
    __shared__ float bsh[64];
    __shared__ float ssh[8][4][128];   // per-warp, 4 rows of staged [msg | interact]

    int t = threadIdx.x, lane = t & 31, wid = t >> 5;
    int dst = (k & 1) ^ 1;

    const float* W1k = W1 + k * 4096;
    const float* W2k = W2 + k * 4096;
    // Wt[i][j] = (i<64) ? W1[k][j][i] : W2[k][j][i-64]
    for (int idx = t; idx < 128 * 32; idx += 256) {
        int i = idx >> 5, l = idx & 31;
        float w0, w1;
        if (i < 64) { w0 = W1k[(2 * l) * 64 + i];      w1 = W1k[(2 * l + 1) * 64 + i]; }
        else        { w0 = W2k[(2 * l) * 64 + i - 64]; w1 = W2k[(2 * l + 1) * 64 + i - 64]; }
        Wsh[idx] = make_float2(w0, w1);
    }
    if (t < 64) bsh[t] = b1[k * 64 + t] + b2[k * 64 + t];
    __syncthreads();

    const int koff = k * 64;
    int r0 = blockIdx.x * rows_per_block;
    int r1 = min(r0 + rows_per_block, N_NODES);

    for (int gbase = r0 + wid * 4; gbase < r1; gbase += 32) {
        // ---- stage s = [msg | msg*x] for 4 rows ----
        #pragma unroll
        for (int rr = 0; rr < 4; ++rr) {
            int r = gbase + rr;
            float2 mv = make_float2(0.f, 0.f), xr = make_float2(0.f, 0.f);
            if (r < r1) {
                mv = __half22float2(__ldcg(&d_msg16[(size_t)r * 32 + lane]));
                xr = *(const float2*)(out + (size_t)r * 256 + koff + 2 * lane);
            }
            float* s = ssh[wid][rr];
            *(float2*)&s[2 * lane]      = mv;
            *(float2*)&s[64 + 2 * lane] = make_float2(mv.x * xr.x, mv.y * xr.y);
        }
        __syncwarp();

        // ---- dense: 4 rows share each W read; lane owns outputs 2l, 2l+1 ----
        unsigned long long binit = pack2(bsh[2 * lane], bsh[2 * lane + 1]);
        unsigned long long acc0 = binit, acc1 = binit, acc2 = binit, acc3 = binit;
        const float2* Wp = Wsh + lane;                  // row i at Wp[i*32]
        const float (*sb)[128] = ssh[wid];
        #pragma unroll
        for (int i = 0; i < 128; i += 4) {
            float2 w0 = Wp[(i + 0) * 32];
            float2 w1 = Wp[(i + 1) * 32];
            float2 w2 = Wp[(i + 2) * 32];
            float2 w3 = Wp[(i + 3) * 32];
            float4 sA = *(const float4*)&sb[0][i];
            float4 sB = *(const float4*)&sb[1][i];
            float4 sC = *(const float4*)&sb[2][i];
            float4 sD = *(const float4*)&sb[3][i];
            ffma2(acc0, sA.x, w0); ffma2(acc0, sA.y, w1);
            ffma2(acc0, sA.z, w2); ffma2(acc0, sA.w, w3);
            ffma2(acc1, sB.x, w0); ffma2(acc1, sB.y, w1);
            ffma2(acc1, sB.z, w2); ffma2(acc1, sB.w, w3);
            ffma2(acc2, sC.x, w0); ffma2(acc2, sC.y, w1);
            ffma2(acc2, sC.z, w2); ffma2(acc2, sC.w, w3);
            ffma2(acc3, sD.x, w0); ffma2(acc3, sD.y, w1);
            ffma2(acc3, sD.z, w2); ffma2(acc3, sD.w, w3);
        }

        // ---- epilogue per row: leaky + warp L2-norm + writes ----
        unsigned long long accs[4] = {acc0, acc1, acc2, acc3};
        #pragma unroll
        for (int rr = 0; rr < 4; ++rr) {
            int r = gbase + rr;
            float h0, h1;
            unpack2(accs[rr], h0, h1);
            h0 = h0 > 0.f ? h0 : 0.2f * h0;             // leaky_relu(0.2)
            h1 = h1 > 0.f ? h1 : 0.2f * h1;
            float sq = h0 * h0 + h1 * h1;
            #pragma unroll
            for (int mm = 16; mm; mm >>= 1)
                sq += __shfl_xor_sync(0xffffffffu, sq, mm);
            float inv = 1.0f / fmaxf(sqrtf(sq), 1e-12f);
            float o0 = h0 * inv, o1 = h1 * inv;
            if (r < r1) {
                *(float2*)(out + (size_t)r * 256 + koff + 64 + 2 * lane) =
                    make_float2(o0, o1);
                if (write16)
                    d_x16[dst][(size_t)r * 32 + lane] = __floats2half2_rn(o0, o1);
            }
        }
        __syncwarp();
    }
}

// ---------------- launch ----------------
extern "C" void kernel_launch(void* const* d_in, const int* in_sizes, int n_in,
                              void* d_out, int out_size) {
    const float* ue   = (const float*)d_in[0];
    const float* ie   = (const float*)d_in[1];
    const float* W1   = (const float*)d_in[2];
    const float* b1   = (const float*)d_in[3];
    const float* W2   = (const float*)d_in[4];
    const float* b2   = (const float*)d_in[5];
    const float* vals = (const float*)d_in[6];
    const int*   rows = (const int*)d_in[7];
    const int*   cols = (const int*)d_in[8];
    float* out = (float*)d_out;
    int e = in_sizes[6];
    int L = in_sizes[2] / (64 * 64);

    // 0) layer-0 embeddings + histogram w/ rank recording
    int GB = (e + 255) / 256;
    k_init_hist<<<GA + GB, 256>>>((const float4*)ue, (const float4*)ie,
                                  (float4*)out, rows, e);
    // 1) rowptr scan (counts self-zeroed)
    k_scan<<<1, 1024>>>(N_NODES);
    // 2) atomic-free scatter
    k_scatter<<<(e + 255) / 256, 256>>>(rows, cols, vals, e);

    // 3..) per layer: gather-tuned spmm, then compute-tuned dense
    const int DGs = 740;                                  // 5 blocks/SM, one wave
    const int rpbs = (N_NODES + DGs - 1) / DGs;           // 203
    const int DGd = 592;                                  // 4 blocks/SM, one wave
    const int rpbd = (N_NODES + DGd - 1) / DGd;           // 254
    for (int k = 0; k < L; ++k) {
        k_spmm<<<DGs, 256>>>(k & 1, rpbs);
        k_dense<<<DGd, 256>>>(W1, b1, W2, b2, out, k, rpbd, (k + 1 < L) ? 1 : 0);
    }
}

// round 15
// speedup vs baseline: 1.1557x; 1.0574x over previous
#include <cuda_runtime.h>
#include <cuda_fp16.h>

#define N_USERS 100000
#define N_NODES 150000
#define E_MAX   4800000
#define SCAN_BLK 1024
#define N_SCAN_BLKS 147   // ceil(150001/1024)

// ---------------- static scratch (no allocation allowed) ----------------
__device__ int  d_counts[N_NODES];          // starts zeroed (.bss), self-zeroed in scanA
__device__ int  d_rowptr[N_NODES + 1];
__device__ int  d_rank[E_MAX];              // intra-row rank of each edge
__device__ int  d_bsums[256];
__device__ int4 d_perm4[E_MAX / 2 + 1];     // {col,val} pairs, 16B-aligned
#define d_perm ((int2*)d_perm4)
__device__ __half2 d_x16[2][N_NODES * 32];  // ping-pong fp16 copy of current x slice
__device__ __half2 d_msg16[N_NODES * 32];   // fp16 msg scratch between spmm and dense

// ------- fused: layer-0 embedding write + histogram (rank-recording) -------
#define GA 9375   // ceil(150000*16/256)

__global__ void k_init_hist(const float4* __restrict__ ue,
                            const float4* __restrict__ ie,
                            float4* __restrict__ out,
                            const int* __restrict__ rows, int e) {
    int b = blockIdx.x, t = threadIdx.x;
    if (b < GA) {
        int i = b * 256 + t;                 // over N_NODES*16
        if (i < N_NODES * 16) {
            int node = i >> 4, d4 = i & 15;
            float4 v = (node < N_USERS) ? ue[node * 16 + d4]
                                        : ie[(node - N_USERS) * 16 + d4];
            out[node * 64 + d4] = v;
            d_x16[0][node * 32 + 2 * d4]     = __floats2half2_rn(v.x, v.y);
            d_x16[0][node * 32 + 2 * d4 + 1] = __floats2half2_rn(v.z, v.w);
        }
    } else {
        int j = (b - GA) * 256 + t;
        if (j < e) {
            int r = __ldcs(&rows[j]);
            d_rank[j] = atomicAdd(&d_counts[r], 1);   // rank doubles as cursor
        }
    }
}

// ------- scanA: block-local exclusive scan + self-zero counts (multi-block) -------
__global__ void k_scanA(int n) {
    __shared__ int sh[SCAN_BLK];
    int t = threadIdx.x;
    int idx = blockIdx.x * SCAN_BLK + t;
    int v = (idx < n) ? d_counts[idx] : 0;
    if (idx < n) d_counts[idx] = 0;              // ready for next replay
    sh[t] = v;
    __syncthreads();
    for (int off = 1; off < SCAN_BLK; off <<= 1) {
        int x = (t >= off) ? sh[t - off] : 0;
        __syncthreads();
        sh[t] += x;
        __syncthreads();
    }
    if (idx <= n) d_rowptr[idx] = sh[t] - v;     // exclusive within block
    if (t == SCAN_BLK - 1) d_bsums[blockIdx.x] = sh[t];
}

// -------- scanBC: each block recomputes global block-prefix, applies it --------
__global__ void k_scanBC(int n) {
    __shared__ int sh[256];
    int t = threadIdx.x, b = blockIdx.x;
    int v = (t < N_SCAN_BLKS) ? d_bsums[t] : 0;
    sh[t] = v;
    __syncthreads();
    for (int off = 1; off < 256; off <<= 1) {    // inclusive scan of bsums
        int x = (t >= off) ? sh[t - off] : 0;
        __syncthreads();
        sh[t] += x;
        __syncthreads();
    }
    int offv = (b > 0) ? sh[b - 1] : 0;
    for (int i = t; i < SCAN_BLK; i += 256) {
        int idx = b * SCAN_BLK + i;
        if (idx <= n) d_rowptr[idx] += offv;
    }
}

// ---------------- scatter: atomic-free (rank precomputed) ----------------
__global__ void k_scatter(const int* __restrict__ rows,
                          const int* __restrict__ cols,
                          const float* __restrict__ vals, int e) {
    int i = blockIdx.x * blockDim.x + threadIdx.x;
    if (i < e) {
        int r = __ldcs(&rows[i]);
        int p = __ldg(&d_rowptr[r]) + __ldcs(&d_rank[i]);
        d_perm[p] = make_int2(__ldcs(&cols[i]), __float_as_int(__ldcs(&vals[i])));
    }
}

// ---------------- packed fp32x2 helpers (Blackwell) ----------------
__device__ __forceinline__ unsigned long long pack2(float a, float b) {
    unsigned long long r;
    asm("mov.b64 %0,{%1,%2};" : "=l"(r) : "f"(a), "f"(b));
    return r;
}
__device__ __forceinline__ void unpack2(unsigned long long v, float& a, float& b) {
    asm("mov.b64 {%0,%1},%2;" : "=f"(a), "=f"(b) : "l"(v));
}
__device__ __forceinline__ void ffma2(unsigned long long& acc, float s, float2 w) {
    asm("{\n\t"
        ".reg .b64 sa, wb;\n\t"
        "mov.b64 sa,{%1,%1};\n\t"
        "mov.b64 wb,{%2,%3};\n\t"
        "fma.rn.f32x2 %0, sa, wb, %0;\n\t"
        "}"
        : "+l"(acc) : "f"(s), "f"(w.x), "f"(w.y));
}

// ---------------- SpMM-only kernel: max residency, no smem ----------------
// warp per row; lane owns dims 2l,2l+1; perm via uniform LDG.128 (2 edges/load);
// unroll-8 for MLP; writes msg fp16. 6 blocks/SM (42-reg cap, ~38 live regs).
__global__ __launch_bounds__(256, 6) void k_spmm(int srck, int rows_per_block) {
    int t = threadIdx.x, lane = t & 31, wid = t >> 5;
    const __half2* __restrict__ xs = d_x16[srck];
    const int2* __restrict__ pm = d_perm;
    const int4* __restrict__ pm4 = d_perm4;

    int r0 = blockIdx.x * rows_per_block;
    int r1 = min(r0 + rows_per_block, N_NODES);

    for (int r = r0 + wid; r < r1; r += 8) {
        int start = __ldg(&d_rowptr[r]);
        int stop  = __ldg(&d_rowptr[r + 1]);
        unsigned long long accA = 0ull, accB = 0ull;
        int e = start;
        if ((e & 1) && e < stop) {                 // align to int4 boundary
            int2 cv = __ldcs(&pm[e]);
            __half2 h = __ldcg(&xs[(size_t)cv.x * 32 + lane]);
            ffma2(accA, __int_as_float(cv.y), __half22float2(h));
            ++e;
        }
        #pragma unroll 1
        for (; e + 8 <= stop; e += 8) {
            int4 p01 = __ldcs(&pm4[(e >> 1) + 0]);
            int4 p23 = __ldcs(&pm4[(e >> 1) + 1]);
            int4 p45 = __ldcs(&pm4[(e >> 1) + 2]);
            int4 p67 = __ldcs(&pm4[(e >> 1) + 3]);
            __half2 h0 = __ldcg(&xs[(size_t)p01.x * 32 + lane]);
            __half2 h1 = __ldcg(&xs[(size_t)p01.z * 32 + lane]);
            __half2 h2 = __ldcg(&xs[(size_t)p23.x * 32 + lane]);
            __half2 h3 = __ldcg(&xs[(size_t)p23.z * 32 + lane]);
            __half2 h4 = __ldcg(&xs[(size_t)p45.x * 32 + lane]);
            __half2 h5 = __ldcg(&xs[(size_t)p45.z * 32 + lane]);
            __half2 h6 = __ldcg(&xs[(size_t)p67.x * 32 + lane]);
            __half2 h7 = __ldcg(&xs[(size_t)p67.z * 32 + lane]);
            ffma2(accA, __int_as_float(p01.y), __half22float2(h0));
            ffma2(accB, __int_as_float(p01.w), __half22float2(h1));
            ffma2(accA, __int_as_float(p23.y), __half22float2(h2));
            ffma2(accB, __int_as_float(p23.w), __half22float2(h3));
            ffma2(accA, __int_as_float(p45.y), __half22float2(h4));
            ffma2(accB, __int_as_float(p45.w), __half22float2(h5));
            ffma2(accA, __int_as_float(p67.y), __half22float2(h6));
            ffma2(accB, __int_as_float(p67.w), __half22float2(h7));
        }
        #pragma unroll 1
        for (; e < stop; ++e) {
            int2 cv = __ldcs(&pm[e]);
            __half2 h = __ldcg(&xs[(size_t)cv.x * 32 + lane]);
            ffma2(accA, __int_as_float(cv.y), __half22float2(h));
        }
        float a0, a1, b0v, b1v;
        unpack2(accA, a0, a1);
        unpack2(accB, b0v, b1v);
        d_msg16[(size_t)r * 32 + lane] = __floats2half2_rn(a0 + b0v, a1 + b1v);
    }
}

// ------- dense-only kernel: 4 rows share each W read + leaky + L2-norm -------
__global__ __launch_bounds__(256, 4) void k_dense(
    const float* __restrict__ W1, const float* __restrict__ b1,
    const float* __restrict__ W2, const float* __restrict__ b2,
    float* out, int k, int rows_per_block, int write16)
{
    __shared__ float2 Wsh[128 * 32];   // [i][l] = float2(Wt[i][2l], Wt[i][2l+1])
    __shared__ float bsh[64];
    __shared__ float ssh[8][4][128];   // per-warp, 4 rows of staged [msg | interact]

    int t = threadIdx.x, lane = t & 31, wid = t >> 5;
    int dst = (k & 1) ^ 1;

    const float* W1k = W1 + k * 4096;
    const float* W2k = W2 + k * 4096;
    // Wt[i][j] = (i<64) ? W1[k][j][i] : W2[k][j][i-64]
    for (int idx = t; idx < 128 * 32; idx += 256) {
        int i = idx >> 5, l = idx & 31;
        float w0, w1;
        if (i < 64) { w0 = W1k[(2 * l) * 64 + i];      w1 = W1k[(2 * l + 1) * 64 + i]; }
        else        { w0 = W2k[(2 * l) * 64 + i - 64]; w1 = W2k[(2 * l + 1) * 64 + i - 64]; }
        Wsh[idx] = make_float2(w0, w1);
    }
    if (t < 64) bsh[t] = b1[k * 64 + t] + b2[k * 64 + t];
    __syncthreads();

    const int koff = k * 64;
    int r0 = blockIdx.x * rows_per_block;
    int r1 = min(r0 + rows_per_block, N_NODES);

    for (int gbase = r0 + wid * 4; gbase < r1; gbase += 32) {
        // ---- stage s = [msg | msg*x] for 4 rows ----
        #pragma unroll
        for (int rr = 0; rr < 4; ++rr) {
            int r = gbase + rr;
            float2 mv = make_float2(0.f, 0.f), xr = make_float2(0.f, 0.f);
            if (r < r1) {
                mv = __half22float2(__ldcg(&d_msg16[(size_t)r * 32 + lane]));
                xr = *(const float2*)(out + (size_t)r * 256 + koff + 2 * lane);
            }
            float* s = ssh[wid][rr];
            *(float2*)&s[2 * lane]      = mv;
            *(float2*)&s[64 + 2 * lane] = make_float2(mv.x * xr.x, mv.y * xr.y);
        }
        __syncwarp();

        // ---- dense: 4 rows share each W read; lane owns outputs 2l, 2l+1 ----
        unsigned long long binit = pack2(bsh[2 * lane], bsh[2 * lane + 1]);
        unsigned long long acc0 = binit, acc1 = binit, acc2 = binit, acc3 = binit;
        const float2* Wp = Wsh + lane;                  // row i at Wp[i*32]
        const float (*sb)[128] = ssh[wid];
        #pragma unroll
        for (int i = 0; i < 128; i += 4) {
            float2 w0 = Wp[(i + 0) * 32];
            float2 w1 = Wp[(i + 1) * 32];
            float2 w2 = Wp[(i + 2) * 32];
            float2 w3 = Wp[(i + 3) * 32];
            float4 sA = *(const float4*)&sb[0][i];
            float4 sB = *(const float4*)&sb[1][i];
            float4 sC = *(const float4*)&sb[2][i];
            float4 sD = *(const float4*)&sb[3][i];
            ffma2(acc0, sA.x, w0); ffma2(acc0, sA.y, w1);
            ffma2(acc0, sA.z, w2); ffma2(acc0, sA.w, w3);
            ffma2(acc1, sB.x, w0); ffma2(acc1, sB.y, w1);
            ffma2(acc1, sB.z, w2); ffma2(acc1, sB.w, w3);
            ffma2(acc2, sC.x, w0); ffma2(acc2, sC.y, w1);
            ffma2(acc2, sC.z, w2); ffma2(acc2, sC.w, w3);
            ffma2(acc3, sD.x, w0); ffma2(acc3, sD.y, w1);
            ffma2(acc3, sD.z, w2); ffma2(acc3, sD.w, w3);
        }

        // ---- epilogue per row: leaky + warp L2-norm + writes ----
        unsigned long long accs[4] = {acc0, acc1, acc2, acc3};
        #pragma unroll
        for (int rr = 0; rr < 4; ++rr) {
            int r = gbase + rr;
            float h0, h1;
            unpack2(accs[rr], h0, h1);
            h0 = h0 > 0.f ? h0 : 0.2f * h0;             // leaky_relu(0.2)
            h1 = h1 > 0.f ? h1 : 0.2f * h1;
            float sq = h0 * h0 + h1 * h1;
            #pragma unroll
            for (int mm = 16; mm; mm >>= 1)
                sq += __shfl_xor_sync(0xffffffffu, sq, mm);
            float inv = 1.0f / fmaxf(sqrtf(sq), 1e-12f);
            float o0 = h0 * inv, o1 = h1 * inv;
            if (r < r1) {
                *(float2*)(out + (size_t)r * 256 + koff + 64 + 2 * lane) =
                    make_float2(o0, o1);
                if (write16)
                    d_x16[dst][(size_t)r * 32 + lane] = __floats2half2_rn(o0, o1);
            }
        }
        __syncwarp();
    }
}

// ---------------- launch ----------------
extern "C" void kernel_launch(void* const* d_in, const int* in_sizes, int n_in,
                              void* d_out, int out_size) {
    const float* ue   = (const float*)d_in[0];
    const float* ie   = (const float*)d_in[1];
    const float* W1   = (const float*)d_in[2];
    const float* b1   = (const float*)d_in[3];
    const float* W2   = (const float*)d_in[4];
    const float* b2   = (const float*)d_in[5];
    const float* vals = (const float*)d_in[6];
    const int*   rows = (const int*)d_in[7];
    const int*   cols = (const int*)d_in[8];
    float* out = (float*)d_out;
    int e = in_sizes[6];
    int L = in_sizes[2] / (64 * 64);

    // 0) layer-0 embeddings + histogram w/ rank recording
    int GB = (e + 255) / 256;
    k_init_hist<<<GA + GB, 256>>>((const float4*)ue, (const float4*)ie,
                                  (float4*)out, rows, e);
    // 1-2) rowptr scan, multi-block (counts self-zeroed in scanA)
    k_scanA<<<N_SCAN_BLKS, SCAN_BLK>>>(N_NODES);
    k_scanBC<<<N_SCAN_BLKS, 256>>>(N_NODES);
    // 3) atomic-free scatter
    k_scatter<<<(e + 255) / 256, 256>>>(rows, cols, vals, e);

    // 4..) per layer: gather-tuned spmm, then compute-tuned dense
    const int DGs = 888;                                  // 6 blocks/SM, one wave
    const int rpbs = (N_NODES + DGs - 1) / DGs;           // 169
    const int DGd = 592;                                  // 4 blocks/SM, one wave
    const int rpbd = (N_NODES + DGd - 1) / DGd;           // 254
    for (int k = 0; k < L; ++k) {
        k_spmm<<<DGs, 256>>>(k & 1, rpbs);
        k_dense<<<DGd, 256>>>(W1, b1, W2, b2, out, k, rpbd, (k + 1 < L) ? 1 : 0);
    }
}

// round 16
// speedup vs baseline: 1.2063x; 1.0438x over previous
#include <cuda_runtime.h>
#include <cuda_fp16.h>

#define N_USERS 100000
#define N_NODES 150000
#define E_MAX   4800000
#define SCAN_BLK 1024
#define N_SCAN_BLKS 147   // ceil(150001/1024)

// ---------------- static scratch (no allocation allowed) ----------------
__device__ int  d_counts[N_NODES];          // starts zeroed (.bss), self-zeroed in scanA
__device__ int  d_rowptr[N_NODES + 1];
__device__ int  d_rank[E_MAX];              // intra-row rank of each edge
__device__ int  d_bsums[256];
__device__ int4 d_perm4[E_MAX / 2 + 1];     // {col,val} pairs, 16B-aligned
#define d_perm ((int2*)d_perm4)
__device__ __half2 d_x16[2][N_NODES * 32];  // ping-pong fp16 copy of current x slice
__device__ __half2 d_msg16[N_NODES * 32];   // fp16 msg scratch between spmm and dense

// ------- fused: layer-0 embedding write + histogram (rank-recording) -------
#define GA 9375   // ceil(150000*16/256)

__global__ void k_init_hist(const float4* __restrict__ ue,
                            const float4* __restrict__ ie,
                            float4* __restrict__ out,
                            const int* __restrict__ rows, int e) {
    int b = blockIdx.x, t = threadIdx.x;
    if (b < GA) {
        int i = b * 256 + t;                 // over N_NODES*16
        if (i < N_NODES * 16) {
            int node = i >> 4, d4 = i & 15;
            float4 v = (node < N_USERS) ? ue[node * 16 + d4]
                                        : ie[(node - N_USERS) * 16 + d4];
            out[node * 64 + d4] = v;
            d_x16[0][node * 32 + 2 * d4]     = __floats2half2_rn(v.x, v.y);
            d_x16[0][node * 32 + 2 * d4 + 1] = __floats2half2_rn(v.z, v.w);
        }
    } else {
        int j = (b - GA) * 256 + t;
        if (j < e) {
            int r = __ldcs(&rows[j]);
            d_rank[j] = atomicAdd(&d_counts[r], 1);   // rank doubles as cursor
        }
    }
}

// ------- scanA: block-local exclusive scan + self-zero counts (multi-block) -------
__global__ void k_scanA(int n) {
    __shared__ int sh[SCAN_BLK];
    int t = threadIdx.x;
    int idx = blockIdx.x * SCAN_BLK + t;
    int v = (idx < n) ? d_counts[idx] : 0;
    if (idx < n) d_counts[idx] = 0;              // ready for next replay
    sh[t] = v;
    __syncthreads();
    for (int off = 1; off < SCAN_BLK; off <<= 1) {
        int x = (t >= off) ? sh[t - off] : 0;
        __syncthreads();
        sh[t] += x;
        __syncthreads();
    }
    if (idx <= n) d_rowptr[idx] = sh[t] - v;     // exclusive within block
    if (t == SCAN_BLK - 1) d_bsums[blockIdx.x] = sh[t];
}

// -------- scanBC: each block recomputes global block-prefix, applies it --------
__global__ void k_scanBC(int n) {
    __shared__ int sh[256];
    int t = threadIdx.x, b = blockIdx.x;
    int v = (t < N_SCAN_BLKS) ? d_bsums[t] : 0;
    sh[t] = v;
    __syncthreads();
    for (int off = 1; off < 256; off <<= 1) {    // inclusive scan of bsums
        int x = (t >= off) ? sh[t - off] : 0;
        __syncthreads();
        sh[t] += x;
        __syncthreads();
    }
    int offv = (b > 0) ? sh[b - 1] : 0;
    for (int i = t; i < SCAN_BLK; i += 256) {
        int idx = b * SCAN_BLK + i;
        if (idx <= n) d_rowptr[idx] += offv;
    }
}

// ---------------- scatter: atomic-free (rank precomputed) ----------------
__global__ void k_scatter(const int* __restrict__ rows,
                          const int* __restrict__ cols,
                          const float* __restrict__ vals, int e) {
    int i = blockIdx.x * blockDim.x + threadIdx.x;
    if (i < e) {
        int r = __ldcs(&rows[i]);
        int p = __ldg(&d_rowptr[r]) + __ldcs(&d_rank[i]);
        d_perm[p] = make_int2(__ldcs(&cols[i]), __float_as_int(__ldcs(&vals[i])));
    }
}

// ---------------- packed fp32x2 helpers (Blackwell) ----------------
__device__ __forceinline__ unsigned long long pack2(float a, float b) {
    unsigned long long r;
    asm("mov.b64 %0,{%1,%2};" : "=l"(r) : "f"(a), "f"(b));
    return r;
}
__device__ __forceinline__ void unpack2(unsigned long long v, float& a, float& b) {
    asm("mov.b64 {%0,%1},%2;" : "=f"(a), "=f"(b) : "l"(v));
}
__device__ __forceinline__ void ffma2(unsigned long long& acc, float s, float2 w) {
    asm("{\n\t"
        ".reg .b64 sa, wb;\n\t"
        "mov.b64 sa,{%1,%1};\n\t"
        "mov.b64 wb,{%2,%3};\n\t"
        "fma.rn.f32x2 %0, sa, wb, %0;\n\t"
        "}"
        : "+l"(acc) : "f"(s), "f"(w.x), "f"(w.y));
}

// ---------------- SpMM-only kernel: max residency, no smem ----------------
// warp per row; lane owns dims 2l,2l+1; perm via uniform LDG.128 (2 edges/load);
// unroll-8 for MLP; writes msg fp16. 6 blocks/SM (42-reg cap, ~38 live regs).
__global__ __launch_bounds__(256, 6) void k_spmm(int srck, int rows_per_block) {
    int t = threadIdx.x, lane = t & 31, wid = t >> 5;
    const __half2* __restrict__ xs = d_x16[srck];
    const int2* __restrict__ pm = d_perm;
    const int4* __restrict__ pm4 = d_perm4;

    int r0 = blockIdx.x * rows_per_block;
    int r1 = min(r0 + rows_per_block, N_NODES);

    for (int r = r0 + wid; r < r1; r += 8) {
        int start = __ldg(&d_rowptr[r]);
        int stop  = __ldg(&d_rowptr[r + 1]);
        unsigned long long accA = 0ull, accB = 0ull;
        int e = start;
        if ((e & 1) && e < stop) {                 // align to int4 boundary
            int2 cv = __ldcs(&pm[e]);
            __half2 h = __ldcg(&xs[(size_t)cv.x * 32 + lane]);
            ffma2(accA, __int_as_float(cv.y), __half22float2(h));
            ++e;
        }
        #pragma unroll 1
        for (; e + 8 <= stop; e += 8) {
            int4 p01 = __ldcs(&pm4[(e >> 1) + 0]);
            int4 p23 = __ldcs(&pm4[(e >> 1) + 1]);
            int4 p45 = __ldcs(&pm4[(e >> 1) + 2]);
            int4 p67 = __ldcs(&pm4[(e >> 1) + 3]);
            __half2 h0 = __ldcg(&xs[(size_t)p01.x * 32 + lane]);
            __half2 h1 = __ldcg(&xs[(size_t)p01.z * 32 + lane]);
            __half2 h2 = __ldcg(&xs[(size_t)p23.x * 32 + lane]);
            __half2 h3 = __ldcg(&xs[(size_t)p23.z * 32 + lane]);
            __half2 h4 = __ldcg(&xs[(size_t)p45.x * 32 + lane]);
            __half2 h5 = __ldcg(&xs[(size_t)p45.z * 32 + lane]);
            __half2 h6 = __ldcg(&xs[(size_t)p67.x * 32 + lane]);
            __half2 h7 = __ldcg(&xs[(size_t)p67.z * 32 + lane]);
            ffma2(accA, __int_as_float(p01.y), __half22float2(h0));
            ffma2(accB, __int_as_float(p01.w), __half22float2(h1));
            ffma2(accA, __int_as_float(p23.y), __half22float2(h2));
            ffma2(accB, __int_as_float(p23.w), __half22float2(h3));
            ffma2(accA, __int_as_float(p45.y), __half22float2(h4));
            ffma2(accB, __int_as_float(p45.w), __half22float2(h5));
            ffma2(accA, __int_as_float(p67.y), __half22float2(h6));
            ffma2(accB, __int_as_float(p67.w), __half22float2(h7));
        }
        #pragma unroll 1
        for (; e < stop; ++e) {
            int2 cv = __ldcs(&pm[e]);
            __half2 h = __ldcg(&xs[(size_t)cv.x * 32 + lane]);
            ffma2(accA, __int_as_float(cv.y), __half22float2(h));
        }
        float a0, a1, b0v, b1v;
        unpack2(accA, a0, a1);
        unpack2(accB, b0v, b1v);
        d_msg16[(size_t)r * 32 + lane] = __floats2half2_rn(a0 + b0v, a1 + b1v);
    }
}

// ------- dense-only kernel: 8 rows share each fp16-W read + leaky + L2-norm -------
// dynamic smem: Wsh(16KB half2) | bsh(256B) | ssh 8 warps x 8 rows x 128 f (32KB)
#define DSM_DENSE (16384 + 256 + 32768)

__global__ __launch_bounds__(256, 4) void k_dense(
    const float* __restrict__ W1, const float* __restrict__ b1,
    const float* __restrict__ W2, const float* __restrict__ b2,
    float* out, int k, int rows_per_block, int write16)
{
    extern __shared__ char dsm[];
    __half2* Wsh = (__half2*)dsm;                 // [i*32 + l] = half2(Wt[i][2l], Wt[i][2l+1])
    float* bsh = (float*)(dsm + 16384);
    float* ssh = (float*)(dsm + 16384 + 256);     // [wid*1024 + rr*128 + i]

    int t = threadIdx.x, lane = t & 31, wid = t >> 5;
    int src = k & 1, dst = src ^ 1;
    const __half2* __restrict__ xs = d_x16[src];

    const float* W1k = W1 + k * 4096;
    const float* W2k = W2 + k * 4096;
    // Wt[i][j] = (i<64) ? W1[k][j][i] : W2[k][j][i-64]
    for (int idx = t; idx < 128 * 32; idx += 256) {
        int i = idx >> 5, l = idx & 31;
        float w0, w1;
        if (i < 64) { w0 = W1k[(2 * l) * 64 + i];      w1 = W1k[(2 * l + 1) * 64 + i]; }
        else        { w0 = W2k[(2 * l) * 64 + i - 64]; w1 = W2k[(2 * l + 1) * 64 + i - 64]; }
        Wsh[idx] = __floats2half2_rn(w0, w1);
    }
    if (t < 64) bsh[t] = b1[k * 64 + t] + b2[k * 64 + t];
    __syncthreads();

    const int koff = k * 64;
    int r0 = blockIdx.x * rows_per_block;
    int r1 = min(r0 + rows_per_block, N_NODES);

    for (int gbase = r0 + wid * 8; gbase < r1; gbase += 64) {
        // ---- stage s = [msg | msg*x] for 8 rows (msg + x both fp16 streams) ----
        float* sw = ssh + wid * 1024;
        #pragma unroll
        for (int rr = 0; rr < 8; ++rr) {
            int r = gbase + rr;
            float2 mv = make_float2(0.f, 0.f), xr = make_float2(0.f, 0.f);
            if (r < r1) {
                mv = __half22float2(__ldcg(&d_msg16[(size_t)r * 32 + lane]));
                xr = __half22float2(__ldcg(&xs[(size_t)r * 32 + lane]));
            }
            float* s = sw + rr * 128;
            *(float2*)&s[2 * lane]      = mv;
            *(float2*)&s[64 + 2 * lane] = make_float2(mv.x * xr.x, mv.y * xr.y);
        }
        __syncwarp();

        // ---- dense: 8 rows share each W read; lane owns outputs 2l, 2l+1 ----
        unsigned long long binit = pack2(bsh[2 * lane], bsh[2 * lane + 1]);
        unsigned long long acc[8];
        #pragma unroll
        for (int rr = 0; rr < 8; ++rr) acc[rr] = binit;
        const __half2* Wp = Wsh + lane;               // row i at Wp[i*32]
        #pragma unroll
        for (int i = 0; i < 128; i += 4) {
            float2 w0 = __half22float2(Wp[(i + 0) * 32]);
            float2 w1 = __half22float2(Wp[(i + 1) * 32]);
            float2 w2 = __half22float2(Wp[(i + 2) * 32]);
            float2 w3 = __half22float2(Wp[(i + 3) * 32]);
            #pragma unroll
            for (int rr = 0; rr < 8; ++rr) {
                float4 s4 = *(const float4*)&sw[rr * 128 + i];   // broadcast
                ffma2(acc[rr], s4.x, w0);
                ffma2(acc[rr], s4.y, w1);
                ffma2(acc[rr], s4.z, w2);
                ffma2(acc[rr], s4.w, w3);
            }
        }

        // ---- epilogue per row: leaky + warp L2-norm + writes ----
        #pragma unroll
        for (int rr = 0; rr < 8; ++rr) {
            int r = gbase + rr;
            float h0, h1;
            unpack2(acc[rr], h0, h1);
            h0 = h0 > 0.f ? h0 : 0.2f * h0;             // leaky_relu(0.2)
            h1 = h1 > 0.f ? h1 : 0.2f * h1;
            float sq = h0 * h0 + h1 * h1;
            #pragma unroll
            for (int mm = 16; mm; mm >>= 1)
                sq += __shfl_xor_sync(0xffffffffu, sq, mm);
            float inv = 1.0f / fmaxf(sqrtf(sq), 1e-12f);
            float o0 = h0 * inv, o1 = h1 * inv;
            if (r < r1) {
                *(float2*)(out + (size_t)r * 256 + koff + 64 + 2 * lane) =
                    make_float2(o0, o1);
                if (write16)
                    d_x16[dst][(size_t)r * 32 + lane] = __floats2half2_rn(o0, o1);
            }
        }
        __syncwarp();
    }
}

// ---------------- launch ----------------
extern "C" void kernel_launch(void* const* d_in, const int* in_sizes, int n_in,
                              void* d_out, int out_size) {
    const float* ue   = (const float*)d_in[0];
    const float* ie   = (const float*)d_in[1];
    const float* W1   = (const float*)d_in[2];
    const float* b1   = (const float*)d_in[3];
    const float* W2   = (const float*)d_in[4];
    const float* b2   = (const float*)d_in[5];
    const float* vals = (const float*)d_in[6];
    const int*   rows = (const int*)d_in[7];
    const int*   cols = (const int*)d_in[8];
    float* out = (float*)d_out;
    int e = in_sizes[6];
    int L = in_sizes[2] / (64 * 64);

    static int smem_set = 0;
    if (!smem_set) {
        cudaFuncSetAttribute(k_dense, cudaFuncAttributeMaxDynamicSharedMemorySize,
                             DSM_DENSE);
        smem_set = 1;
    }

    // 0) layer-0 embeddings + histogram w/ rank recording
    int GB = (e + 255) / 256;
    k_init_hist<<<GA + GB, 256>>>((const float4*)ue, (const float4*)ie,
                                  (float4*)out, rows, e);
    // 1-2) rowptr scan, multi-block (counts self-zeroed in scanA)
    k_scanA<<<N_SCAN_BLKS, SCAN_BLK>>>(N_NODES);
    k_scanBC<<<N_SCAN_BLKS, 256>>>(N_NODES);
    // 3) atomic-free scatter
    k_scatter<<<(e + 255) / 256, 256>>>(rows, cols, vals, e);

    // 4..) per layer: gather-tuned spmm, then compute-tuned dense
    const int DGs = 888;                                  // 6 blocks/SM, one wave
    const int rpbs = (N_NODES + DGs - 1) / DGs;           // 169
    const int DGd = 592;                                  // 4 blocks/SM, one wave
    const int rpbd = (N_NODES + DGd - 1) / DGd;           // 254
    for (int k = 0; k < L; ++k) {
        k_spmm<<<DGs, 256>>>(k & 1, rpbs);
        k_dense<<<DGd, 256, DSM_DENSE>>>(W1, b1, W2, b2, out, k, rpbd,
                                         (k + 1 < L) ? 1 : 0);
    }
}

// round 17
// speedup vs baseline: 1.2642x; 1.0480x over previous
#include <cuda_runtime.h>
#include <cuda_fp16.h>

#define N_USERS 100000
#define N_NODES 150000
#define E_MAX   4800000
#define SCAN_BLK 1024
#define N_SCAN_BLKS 147   // ceil(150001/1024)

// ---------------- static scratch (no allocation allowed) ----------------
__device__ int  d_counts[N_NODES];          // starts zeroed (.bss), self-zeroed in scanA
__device__ int  d_rowptr[N_NODES + 1];
__device__ int  d_rank[E_MAX];              // intra-row rank of each edge
__device__ int  d_bsums[256];
__device__ int4 d_perm4[E_MAX / 2 + 1];     // {col,val} pairs, 16B-aligned
#define d_perm ((int2*)d_perm4)
__device__ __half2 d_x16[2][N_NODES * 32];  // ping-pong fp16 copy of current x slice
__device__ __half2 d_msg16[N_NODES * 32];   // fp16 msg scratch between spmm and dense

// ------- fused: layer-0 embedding write + histogram (rank-recording) -------
#define GA 9375   // ceil(150000*16/256)

__global__ void k_init_hist(const float4* __restrict__ ue,
                            const float4* __restrict__ ie,
                            float4* __restrict__ out,
                            const int* __restrict__ rows, int e) {
    int b = blockIdx.x, t = threadIdx.x;
    if (b < GA) {
        int i = b * 256 + t;                 // over N_NODES*16
        if (i < N_NODES * 16) {
            int node = i >> 4, d4 = i & 15;
            float4 v = (node < N_USERS) ? ue[node * 16 + d4]
                                        : ie[(node - N_USERS) * 16 + d4];
            out[node * 64 + d4] = v;
            d_x16[0][node * 32 + 2 * d4]     = __floats2half2_rn(v.x, v.y);
            d_x16[0][node * 32 + 2 * d4 + 1] = __floats2half2_rn(v.z, v.w);
        }
    } else {
        int j = (b - GA) * 256 + t;
        if (j < e) {
            int r = __ldcs(&rows[j]);
            d_rank[j] = atomicAdd(&d_counts[r], 1);   // rank doubles as cursor
        }
    }
}

// ------- scanA: block-local exclusive scan + self-zero counts (multi-block) -------
__global__ void k_scanA(int n) {
    __shared__ int sh[SCAN_BLK];
    int t = threadIdx.x;
    int idx = blockIdx.x * SCAN_BLK + t;
    int v = (idx < n) ? d_counts[idx] : 0;
    if (idx < n) d_counts[idx] = 0;              // ready for next replay
    sh[t] = v;
    __syncthreads();
    for (int off = 1; off < SCAN_BLK; off <<= 1) {
        int x = (t >= off) ? sh[t - off] : 0;
        __syncthreads();
        sh[t] += x;
        __syncthreads();
    }
    if (idx <= n) d_rowptr[idx] = sh[t] - v;     // exclusive within block
    if (t == SCAN_BLK - 1) d_bsums[blockIdx.x] = sh[t];
}

// -------- scanBC: each block recomputes global block-prefix, applies it --------
__global__ void k_scanBC(int n) {
    __shared__ int sh[256];
    int t = threadIdx.x, b = blockIdx.x;
    int v = (t < N_SCAN_BLKS) ? d_bsums[t] : 0;
    sh[t] = v;
    __syncthreads();
    for (int off = 1; off < 256; off <<= 1) {    // inclusive scan of bsums
        int x = (t >= off) ? sh[t - off] : 0;
        __syncthreads();
        sh[t] += x;
        __syncthreads();
    }
    int offv = (b > 0) ? sh[b - 1] : 0;
    for (int i = t; i < SCAN_BLK; i += 256) {
        int idx = b * SCAN_BLK + i;
        if (idx <= n) d_rowptr[idx] += offv;
    }
}

// ---------------- scatter: atomic-free (rank precomputed) ----------------
__global__ void k_scatter(const int* __restrict__ rows,
                          const int* __restrict__ cols,
                          const float* __restrict__ vals, int e) {
    int i = blockIdx.x * blockDim.x + threadIdx.x;
    if (i < e) {
        int r = __ldcs(&rows[i]);
        int p = __ldg(&d_rowptr[r]) + __ldcs(&d_rank[i]);
        d_perm[p] = make_int2(__ldcs(&cols[i]), __float_as_int(__ldcs(&vals[i])));
    }
}

// ---------------- packed fp32x2 helpers (Blackwell) ----------------
__device__ __forceinline__ unsigned long long pack2(float a, float b) {
    unsigned long long r;
    asm("mov.b64 %0,{%1,%2};" : "=l"(r) : "f"(a), "f"(b));
    return r;
}
__device__ __forceinline__ void unpack2(unsigned long long v, float& a, float& b) {
    asm("mov.b64 {%0,%1},%2;" : "=f"(a), "=f"(b) : "l"(v));
}
__device__ __forceinline__ void ffma2(unsigned long long& acc, float s, float2 w) {
    asm("{\n\t"
        ".reg .b64 sa, wb;\n\t"
        "mov.b64 sa,{%1,%1};\n\t"
        "mov.b64 wb,{%2,%3};\n\t"
        "fma.rn.f32x2 %0, sa, wb, %0;\n\t"
        "}"
        : "+l"(acc) : "f"(s), "f"(w.x), "f"(w.y));
}

// ---------------- SpMM-only kernel: LDG-rate optimized ----------------
// Half-warp per edge: lane m<16 holds dims 4m..4m+3 (uint2 = 2 half2 per load),
// so each warp-LDG serves 2 edges -> 32 LDG/row vs 48. Final shfl-xor(16)
// folds the two half-warp partial sums. Lanes 0-15 write msg (128B/row).
__global__ __launch_bounds__(256, 5) void k_spmm(int srck, int rows_per_block) {
    int t = threadIdx.x, lane = t & 31, wid = t >> 5;
    int half = lane >> 4, m = lane & 15;
    const __half2* __restrict__ xs = d_x16[srck];
    const int2* __restrict__ pm = d_perm;
    const int4* __restrict__ pm4 = d_perm4;

    int r0 = blockIdx.x * rows_per_block;
    int r1 = min(r0 + rows_per_block, N_NODES);

    for (int r = r0 + wid; r < r1; r += 8) {
        int start = __ldg(&d_rowptr[r]);
        int stop  = __ldg(&d_rowptr[r + 1]);
        unsigned long long accA = 0ull, accB = 0ull;   // dims 4m..4m+1, 4m+2..4m+3
        int e = start;
        if ((e & 1) && e < stop) {                 // align to int4 boundary
            int2 cv = __ldcs(&pm[e]);
            uint2 hx = __ldcg((const uint2*)(xs + (size_t)cv.x * 32) + m);
            float v = (half == 0) ? __int_as_float(cv.y) : 0.f;
            ffma2(accA, v, __half22float2(*(__half2*)&hx.x));
            ffma2(accB, v, __half22float2(*(__half2*)&hx.y));
            ++e;
        }
        #pragma unroll 1
        for (; e + 8 <= stop; e += 8) {
            int4 p0 = __ldcs(&pm4[(e >> 1) + 0]);  // edges e+0, e+1
            int4 p1 = __ldcs(&pm4[(e >> 1) + 1]);  // edges e+2, e+3
            int4 p2 = __ldcs(&pm4[(e >> 1) + 2]);  // edges e+4, e+5
            int4 p3 = __ldcs(&pm4[(e >> 1) + 3]);  // edges e+6, e+7
            int   c0 = half ? p0.z : p0.x;  float v0 = __int_as_float(half ? p0.w : p0.y);
            int   c1 = half ? p1.z : p1.x;  float v1 = __int_as_float(half ? p1.w : p1.y);
            int   c2 = half ? p2.z : p2.x;  float v2 = __int_as_float(half ? p2.w : p2.y);
            int   c3 = half ? p3.z : p3.x;  float v3 = __int_as_float(half ? p3.w : p3.y);
            uint2 h0 = __ldcg((const uint2*)(xs + (size_t)c0 * 32) + m);
            uint2 h1 = __ldcg((const uint2*)(xs + (size_t)c1 * 32) + m);
            uint2 h2 = __ldcg((const uint2*)(xs + (size_t)c2 * 32) + m);
            uint2 h3 = __ldcg((const uint2*)(xs + (size_t)c3 * 32) + m);
            ffma2(accA, v0, __half22float2(*(__half2*)&h0.x));
            ffma2(accB, v0, __half22float2(*(__half2*)&h0.y));
            ffma2(accA, v1, __half22float2(*(__half2*)&h1.x));
            ffma2(accB, v1, __half22float2(*(__half2*)&h1.y));
            ffma2(accA, v2, __half22float2(*(__half2*)&h2.x));
            ffma2(accB, v2, __half22float2(*(__half2*)&h2.y));
            ffma2(accA, v3, __half22float2(*(__half2*)&h3.x));
            ffma2(accB, v3, __half22float2(*(__half2*)&h3.y));
        }
        #pragma unroll 1
        for (; e < stop; e += 2) {                 // remainder, 2 at a time
            int ee = e + half;
            int2 cv = __ldcs(&pm[min(ee, stop - 1)]);
            float v = (ee < stop) ? __int_as_float(cv.y) : 0.f;
            uint2 hx = __ldcg((const uint2*)(xs + (size_t)cv.x * 32) + m);
            ffma2(accA, v, __half22float2(*(__half2*)&hx.x));
            ffma2(accB, v, __half22float2(*(__half2*)&hx.y));
        }
        float a0, a1, a2, a3;
        unpack2(accA, a0, a1);
        unpack2(accB, a2, a3);
        a0 += __shfl_xor_sync(0xffffffffu, a0, 16);
        a1 += __shfl_xor_sync(0xffffffffu, a1, 16);
        a2 += __shfl_xor_sync(0xffffffffu, a2, 16);
        a3 += __shfl_xor_sync(0xffffffffu, a3, 16);
        if (half == 0) {
            uint2 o;
            __half2 o01 = __floats2half2_rn(a0, a1);
            __half2 o23 = __floats2half2_rn(a2, a3);
            o.x = *(unsigned*)&o01;
            o.y = *(unsigned*)&o23;
            *((uint2*)(d_msg16 + (size_t)r * 32) + m) = o;
        }
    }
}

// ------- dense-only kernel: 8 rows share each fp16-W read + leaky + L2-norm -------
// dynamic smem: Wsh(16KB half2) | bsh(256B) | ssh 8 warps x 8 rows x 128 f (32KB)
#define DSM_DENSE (16384 + 256 + 32768)

__global__ __launch_bounds__(256, 4) void k_dense(
    const float* __restrict__ W1, const float* __restrict__ b1,
    const float* __restrict__ W2, const float* __restrict__ b2,
    float* out, int k, int rows_per_block, int write16)
{
    extern __shared__ char dsm[];
    __half2* Wsh = (__half2*)dsm;                 // [i*32 + l] = half2(Wt[i][2l], Wt[i][2l+1])
    float* bsh = (float*)(dsm + 16384);
    float* ssh = (float*)(dsm + 16384 + 256);     // [wid*1024 + rr*128 + i]

    int t = threadIdx.x, lane = t & 31, wid = t >> 5;
    int src = k & 1, dst = src ^ 1;
    const __half2* __restrict__ xs = d_x16[src];

    const float* W1k = W1 + k * 4096;
    const float* W2k = W2 + k * 4096;
    // Wt[i][j] = (i<64) ? W1[k][j][i] : W2[k][j][i-64]
    for (int idx = t; idx < 128 * 32; idx += 256) {
        int i = idx >> 5, l = idx & 31;
        float w0, w1;
        if (i < 64) { w0 = W1k[(2 * l) * 64 + i];      w1 = W1k[(2 * l + 1) * 64 + i]; }
        else        { w0 = W2k[(2 * l) * 64 + i - 64]; w1 = W2k[(2 * l + 1) * 64 + i - 64]; }
        Wsh[idx] = __floats2half2_rn(w0, w1);
    }
    if (t < 64) bsh[t] = b1[k * 64 + t] + b2[k * 64 + t];
    __syncthreads();

    const int koff = k * 64;
    int r0 = blockIdx.x * rows_per_block;
    int r1 = min(r0 + rows_per_block, N_NODES);

    for (int gbase = r0 + wid * 8; gbase < r1; gbase += 64) {
        // ---- stage s = [msg | msg*x] for 8 rows (msg + x both fp16 streams) ----
        float* sw = ssh + wid * 1024;
        #pragma unroll
        for (int rr = 0; rr < 8; ++rr) {
            int r = gbase + rr;
            float2 mv = make_float2(0.f, 0.f), xr = make_float2(0.f, 0.f);
            if (r < r1) {
                mv = __half22float2(__ldcg(&d_msg16[(size_t)r * 32 + lane]));
                xr = __half22float2(__ldcg(&xs[(size_t)r * 32 + lane]));
            }
            float* s = sw + rr * 128;
            *(float2*)&s[2 * lane]      = mv;
            *(float2*)&s[64 + 2 * lane] = make_float2(mv.x * xr.x, mv.y * xr.y);
        }
        __syncwarp();

        // ---- dense: 8 rows share each W read; lane owns outputs 2l, 2l+1 ----
        unsigned long long binit = pack2(bsh[2 * lane], bsh[2 * lane + 1]);
        unsigned long long acc[8];
        #pragma unroll
        for (int rr = 0; rr < 8; ++rr) acc[rr] = binit;
        const __half2* Wp = Wsh + lane;               // row i at Wp[i*32]
        #pragma unroll
        for (int i = 0; i < 128; i += 4) {
            float2 w0 = __half22float2(Wp[(i + 0) * 32]);
            float2 w1 = __half22float2(Wp[(i + 1) * 32]);
            float2 w2 = __half22float2(Wp[(i + 2) * 32]);
            float2 w3 = __half22float2(Wp[(i + 3) * 32]);
            #pragma unroll
            for (int rr = 0; rr < 8; ++rr) {
                float4 s4 = *(const float4*)&sw[rr * 128 + i];   // broadcast
                ffma2(acc[rr], s4.x, w0);
                ffma2(acc[rr], s4.y, w1);
                ffma2(acc[rr], s4.z, w2);
                ffma2(acc[rr], s4.w, w3);
            }
        }

        // ---- epilogue per row: leaky + warp L2-norm + writes ----
        #pragma unroll
        for (int rr = 0; rr < 8; ++rr) {
            int r = gbase + rr;
            float h0, h1;
            unpack2(acc[rr], h0, h1);
            h0 = h0 > 0.f ? h0 : 0.2f * h0;             // leaky_relu(0.2)
            h1 = h1 > 0.f ? h1 : 0.2f * h1;
            float sq = h0 * h0 + h1 * h1;
            #pragma unroll
            for (int mm = 16; mm; mm >>= 1)
                sq += __shfl_xor_sync(0xffffffffu, sq, mm);
            float inv = 1.0f / fmaxf(sqrtf(sq), 1e-12f);
            float o0 = h0 * inv, o1 = h1 * inv;
            if (r < r1) {
                *(float2*)(out + (size_t)r * 256 + koff + 64 + 2 * lane) =
                    make_float2(o0, o1);
                if (write16)
                    d_x16[dst][(size_t)r * 32 + lane] = __floats2half2_rn(o0, o1);
            }
        }
        __syncwarp();
    }
}

// ---------------- launch ----------------
extern "C" void kernel_launch(void* const* d_in, const int* in_sizes, int n_in,
                              void* d_out, int out_size) {
    const float* ue   = (const float*)d_in[0];
    const float* ie   = (const float*)d_in[1];
    const float* W1   = (const float*)d_in[2];
    const float* b1   = (const float*)d_in[3];
    const float* W2   = (const float*)d_in[4];
    const float* b2   = (const float*)d_in[5];
    const float* vals = (const float*)d_in[6];
    const int*   rows = (const int*)d_in[7];
    const int*   cols = (const int*)d_in[8];
    float* out = (float*)d_out;
    int e = in_sizes[6];
    int L = in_sizes[2] / (64 * 64);

    static int smem_set = 0;
    if (!smem_set) {
        cudaFuncSetAttribute(k_dense, cudaFuncAttributeMaxDynamicSharedMemorySize,
                             DSM_DENSE);
        smem_set = 1;
    }

    // 0) layer-0 embeddings + histogram w/ rank recording
    int GB = (e + 255) / 256;
    k_init_hist<<<GA + GB, 256>>>((const float4*)ue, (const float4*)ie,
                                  (float4*)out, rows, e);
    // 1-2) rowptr scan, multi-block (counts self-zeroed in scanA)
    k_scanA<<<N_SCAN_BLKS, SCAN_BLK>>>(N_NODES);
    k_scanBC<<<N_SCAN_BLKS, 256>>>(N_NODES);
    // 3) atomic-free scatter
    k_scatter<<<(e + 255) / 256, 256>>>(rows, cols, vals, e);

    // 4..) per layer: gather-tuned spmm, then compute-tuned dense
    const int DGs = 740;                                  // 5 blocks/SM, one wave
    const int rpbs = (N_NODES + DGs - 1) / DGs;           // 203
    const int DGd = 592;                                  // 4 blocks/SM, one wave
    const int rpbd = (N_NODES + DGd - 1) / DGd;           // 254
    for (int k = 0; k < L; ++k) {
        k_spmm<<<DGs, 256>>>(k & 1, rpbs);
        k_dense<<<DGd, 256, DSM_DENSE>>>(W1, b1, W2, b2, out, k, rpbd,
                                         (k + 1 < L) ? 1 : 0);
    }
}